// round 11
// baseline (speedup 1.0000x reference)
#include <cuda_runtime.h>
#include <cuda_fp16.h>
#include <math_constants.h>
#include <cstdint>

#define H 512
#define W 512
#define NB 64
#define HW (H * W)
#define NZ (2 * NB)
#define CPW 120             // valid output columns per warp strip
#define NSTRIP 5            // ceil(512/120)
#define RPW 32              // output rows per warp
#define WPB 8               // warps per block
#define NRG 2               // row groups: 2*8*32 = 512 rows

#define FINF CUDART_INF_F

typedef unsigned int u32;

// Ping-pong fp16 buffers (67 MB each). Referenced ONLY from device code.
__device__ __half g_A[(size_t)NZ * HW];
__device__ __half g_B[(size_t)NZ * HW];
// [0..63] clp*t | [64..127] clp | [128..191] ts*p | [192..255] ts
// [256..319] p*t | [320..383] p | [384..447] t   (per-batch)
__device__ float g_acc[448];

__device__ __forceinline__ u32 h2u(__half2 v) { return *(u32*)&v; }
__device__ __forceinline__ __half2 u2h(u32 u) { return *(__half2*)&u; }

// 4 packed columns per lane: lo = (c0,c1), hi = (c2,c3)
struct W4 { __half2 lo, hi; };

__device__ __forceinline__ W4 bcast4(float f) {
    W4 w; w.lo = __float2half2_rn(f); w.hi = w.lo; return w;
}
__device__ __forceinline__ W4 inf4()  { return bcast4(FINF); }
__device__ __forceinline__ W4 ninf4() { return bcast4(-FINF); }

__device__ __forceinline__ W4 min3w(const W4& a, const W4& b, const W4& c) {
    W4 r;
    r.lo = __hmin2(a.lo, __hmin2(b.lo, c.lo));
    r.hi = __hmin2(a.hi, __hmin2(b.hi, c.hi));
    return r;
}
__device__ __forceinline__ W4 max3w(const W4& a, const W4& b, const W4& c) {
    W4 r;
    r.lo = __hmax2(a.lo, __hmax2(b.lo, c.lo));
    r.hi = __hmax2(a.hi, __hmax2(b.hi, c.hi));
    return r;
}

// Horizontal 3-window min over 4 packed cols; warp-edge lanes garbage
// (shfl wrap) — discarded via the validity margin.
__device__ __forceinline__ W4 hmin4(const W4& v) {
    u32 ulo = h2u(v.lo), uhi = h2u(v.hi);
    u32 lhi = __shfl_up_sync(0xffffffffu, uhi, 1);    // left lane's (c2,c3)
    u32 rlo = __shfl_down_sync(0xffffffffu, ulo, 1);  // right lane's (c0,c1)
    __half2 mid = u2h(__byte_perm(ulo, uhi, 0x5432)); // (x1, x2)
    __half2 shl = u2h(__byte_perm(lhi, ulo, 0x5432)); // (x-1, x0)
    __half2 shr = u2h(__byte_perm(uhi, rlo, 0x5432)); // (x3, x4)
    W4 h;
    h.lo = __hmin2(shl, __hmin2(v.lo, mid));
    h.hi = __hmin2(mid, __hmin2(v.hi, shr));
    return h;
}
__device__ __forceinline__ W4 hmax4(const W4& v) {
    u32 ulo = h2u(v.lo), uhi = h2u(v.hi);
    u32 lhi = __shfl_up_sync(0xffffffffu, uhi, 1);
    u32 rlo = __shfl_down_sync(0xffffffffu, ulo, 1);
    __half2 mid = u2h(__byte_perm(ulo, uhi, 0x5432));
    __half2 shl = u2h(__byte_perm(lhi, ulo, 0x5432));
    __half2 shr = u2h(__byte_perm(uhi, rlo, 0x5432));
    W4 h;
    h.lo = __hmax2(shl, __hmax2(v.lo, mid));
    h.hi = __hmax2(mid, __hmax2(v.hi, shr));
    return h;
}

// Rolling soft-skeletonize pipeline (one iteration stage).
// At base row rb: next step consumes input row rb+2, emits output row rb.
struct Pipe {
    W4 q0, q1;    // input rows rb, rb+1
    W4 hm0, hm1;  // horiz 3-min rows rb, rb+1
    W4 mp0;       // 3x3 min-pool row rb (-inf outside image)
    W4 hxm, hx0;  // horiz 3-max of mp rows rb-1, rb
};

__device__ __forceinline__ void pipe_init(Pipe& s, const W4& va, const W4& vb,
                                          const W4& vc, const W4& vd,
                                          bool okm, bool ok0) {
    W4 ha = hmin4(va), hb = hmin4(vb), hc = hmin4(vc), hd = hmin4(vd);
    W4 mpm = okm ? min3w(ha, hb, hc) : ninf4();
    W4 mp0 = ok0 ? min3w(hb, hc, hd) : ninf4();
    s.hxm = hmax4(mpm); s.hx0 = hmax4(mp0); s.mp0 = mp0;
    s.hm0 = hc; s.hm1 = hd; s.q0 = vc; s.q1 = vd;
}

// Advance one row: consume input row rb+2 (+inf-masked if invalid),
// okp1 = (row rb+1 in image) && colin. Emits output row rb.
__device__ __forceinline__ W4 pipe_step(Pipe& s, const W4& vin, bool okp1) {
    W4 hmn = hmin4(vin);
    W4 mpn = okp1 ? min3w(s.hm0, s.hm1, hmn) : ninf4();
    W4 hxn = hmax4(mpn);
    W4 mx = max3w(s.hxm, s.hx0, hxn);
    __half2 z = __float2half2_rn(0.0f);
    W4 o;
    o.lo = __hmax2(__hsub2(s.q0.lo, __hmax2(__hsub2(mx.lo, s.mp0.lo), z)), z);
    o.hi = __hmax2(__hsub2(s.q0.hi, __hmax2(__hsub2(mx.hi, s.mp0.hi), z)), z);
    s.hxm = s.hx0; s.hx0 = hxn; s.mp0 = mpn;
    s.hm0 = s.hm1; s.hm1 = hmn;
    s.q0 = s.q1; s.q1 = vin;
    return o;
}

// Loads. SAFE variants: no bounds checks at all.
__device__ __forceinline__ W4 ldh4(const __half* __restrict__ p, int r,
                                   int gc, bool colin) {
    if (colin && (unsigned)r < (unsigned)H) {
        uint2 t = *(const uint2*)(p + (size_t)r * W + gc);
        W4 w; w.lo = u2h(t.x); w.hi = u2h(t.y); return w;
    }
    return inf4();
}
__device__ __forceinline__ W4 ldh4u(const __half* __restrict__ p, int r, int gc) {
    uint2 t = *(const uint2*)(p + (size_t)r * W + gc);
    W4 w; w.lo = u2h(t.x); w.hi = u2h(t.y); return w;
}
__device__ __forceinline__ W4 ldf4(const float* __restrict__ p, int r,
                                   int gc, bool colin) {
    if (colin && (unsigned)r < (unsigned)H) {
        float4 f = *(const float4*)(p + (size_t)r * W + gc);
        W4 w; w.lo = __floats2half2_rn(f.x, f.y);
        w.hi = __floats2half2_rn(f.z, f.w); return w;
    }
    return inf4();
}
__device__ __forceinline__ W4 ldf4u(const float* __restrict__ p, int r, int gc) {
    float4 f = *(const float4*)(p + (size_t)r * W + gc);
    W4 w; w.lo = __floats2half2_rn(f.x, f.y);
    w.hi = __floats2half2_rn(f.z, f.w); return w;
}

// ---------------------------------------------------------------------------
// Core: two fused skeletonize iterations, store variant.
// SAFE=true: whole footprint (rows r0-4..r0+RPW+3, cols c0..c0+127) inside
// the image -> zero masking. SAFE=false: full boundary semantics.
// ---------------------------------------------------------------------------
template <bool SAFE, typename LD>
__device__ __forceinline__ void skel_store(LD ld, __half* __restrict__ op,
                                           int r0, int gc, bool colin, bool wr) {
    Pipe s1, s2;
    if (SAFE) {
        pipe_init(s1, ld(r0 - 4), ld(r0 - 3), ld(r0 - 2), ld(r0 - 1), true, true);
        W4 ya = pipe_step(s1, ld(r0),     true);
        W4 yb = pipe_step(s1, ld(r0 + 1), true);
        W4 yc = pipe_step(s1, ld(r0 + 2), true);
        W4 yd = pipe_step(s1, ld(r0 + 3), true);
        pipe_init(s2, ya, yb, yc, yd, true, true);
        size_t off = (size_t)r0 * W + gc;
        #pragma unroll 4
        for (int r = r0; r < r0 + RPW; ++r) {
            W4 y2 = pipe_step(s1, ld(r + 4), true);
            W4 o = pipe_step(s2, y2, true);
            if (wr) {
                uint2 st; st.x = h2u(o.lo); st.y = h2u(o.hi);
                *(uint2*)(op + off) = st;
            }
            off += W;
        }
    } else {
        pipe_init(s1, ld(r0 - 4), ld(r0 - 3), ld(r0 - 2), ld(r0 - 1),
                  colin && (r0 - 3 >= 0), colin && (r0 - 2 >= 0));
        W4 ya = pipe_step(s1, ld(r0),     colin && (r0 - 1 >= 0));
        W4 yb = pipe_step(s1, ld(r0 + 1), colin);
        W4 yc = pipe_step(s1, ld(r0 + 2), colin);
        W4 yd = pipe_step(s1, ld(r0 + 3), colin);
        if (!colin || r0 - 2 < 0) ya = inf4();
        if (!colin || r0 - 1 < 0) yb = inf4();
        if (!colin) { yc = inf4(); yd = inf4(); }
        pipe_init(s2, ya, yb, yc, yd,
                  colin && (r0 - 1 >= 0), colin);
        size_t off = (size_t)r0 * W + gc;
        #pragma unroll 4
        for (int r = r0; r < r0 + RPW; ++r) {
            W4 y2 = pipe_step(s1, ld(r + 4), colin && (r + 3 < H));
            if (!colin || (r + 2 >= H)) y2 = inf4();
            W4 o = pipe_step(s2, y2, colin && (r + 1 < H));
            if (wr) {
                uint2 st; st.x = h2u(o.lo); st.y = h2u(o.hi);
                *(uint2*)(op + off) = st;
            }
            off += W;
        }
    }
}

// ---------------------------------------------------------------------------
// mode 0: fp32 inputs -> g_A;  mode 1: g_A -> g_B;  mode 2: g_B -> g_A
// ---------------------------------------------------------------------------
__global__ void __launch_bounds__(256)
skel2(int mode, const float* __restrict__ pred,
      const float* __restrict__ target) {
    const int z = blockIdx.y;
    const int lane = threadIdx.x & 31;
    const int warp = threadIdx.x >> 5;
    const int c0 = blockIdx.x * CPW - 4;
    const int gc = c0 + lane * 4;
    const bool colin = (gc >= 0) && (gc < W);
    const bool wr = (lane >= 1) && (lane <= 30) && colin;
    const int r0 = (blockIdx.z * WPB + warp) * RPW;
    const bool safe = (c0 >= 0) && (c0 + 128 <= W) &&
                      (r0 >= 4) && (r0 + RPW + 4 <= H);

    const float* __restrict__ xf = nullptr;
    const __half* __restrict__ xh = nullptr;
    __half* __restrict__ op;
    if (mode == 0) {
        xf = (z < NB) ? pred + (size_t)z * HW : target + (size_t)(z - NB) * HW;
        op = g_A + (size_t)z * HW;
    } else if (mode == 1) {
        xh = g_A + (size_t)z * HW; op = g_B + (size_t)z * HW;
    } else {
        xh = g_B + (size_t)z * HW; op = g_A + (size_t)z * HW;
    }

    if (mode == 0) {
        if (safe) {
            auto ld = [&](int r) { return ldf4u(xf, r, gc); };
            skel_store<true>(ld, op, r0, gc, colin, wr);
        } else {
            auto ld = [&](int r) { return ldf4(xf, r, gc, colin); };
            skel_store<false>(ld, op, r0, gc, colin, wr);
        }
    } else {
        if (safe) {
            auto ld = [&](int r) { return ldh4u(xh, r, gc); };
            skel_store<true>(ld, op, r0, gc, colin, wr);
        } else {
            auto ld = [&](int r) { return ldh4(xh, r, gc, colin); };
            skel_store<false>(ld, op, r0, gc, colin, wr);
        }
    }
}

// ---------------------------------------------------------------------------
// Final two iterations fused with all reductions (reads g_B, writes g_acc).
// ---------------------------------------------------------------------------
template <bool SAFE>
__device__ __forceinline__ void skel_accum(const __half* __restrict__ xp,
                                           const float* __restrict__ pb,
                                           const float* __restrict__ tb,
                                           int z, int r0, int gc,
                                           bool colin, bool wr,
                                           float& s0, float& s1a, float& s2a,
                                           float& s3, float& s4) {
    Pipe s1, s2;
    auto lds = [&](int r) { return SAFE ? ldh4u(xp, r, gc)
                                        : ldh4(xp, r, gc, colin); };
    if (SAFE) {
        pipe_init(s1, lds(r0 - 4), lds(r0 - 3), lds(r0 - 2), lds(r0 - 1), true, true);
        W4 ya = pipe_step(s1, lds(r0),     true);
        W4 yb = pipe_step(s1, lds(r0 + 1), true);
        W4 yc = pipe_step(s1, lds(r0 + 2), true);
        W4 yd = pipe_step(s1, lds(r0 + 3), true);
        pipe_init(s2, ya, yb, yc, yd, true, true);
    } else {
        pipe_init(s1, lds(r0 - 4), lds(r0 - 3), lds(r0 - 2), lds(r0 - 1),
                  colin && (r0 - 3 >= 0), colin && (r0 - 2 >= 0));
        W4 ya = pipe_step(s1, lds(r0),     colin && (r0 - 1 >= 0));
        W4 yb = pipe_step(s1, lds(r0 + 1), colin);
        W4 yc = pipe_step(s1, lds(r0 + 2), colin);
        W4 yd = pipe_step(s1, lds(r0 + 3), colin);
        if (!colin || r0 - 2 < 0) ya = inf4();
        if (!colin || r0 - 1 < 0) yb = inf4();
        if (!colin) { yc = inf4(); yd = inf4(); }
        pipe_init(s2, ya, yb, yc, yd, colin && (r0 - 1 >= 0), colin);
    }

    size_t off = (size_t)r0 * W + gc;
    #pragma unroll 4
    for (int r = r0; r < r0 + RPW; ++r) {
        W4 y2 = pipe_step(s1, lds(r + 4), SAFE ? true : (colin && (r + 3 < H)));
        if (!SAFE) { if (!colin || (r + 2 >= H)) y2 = inf4(); }
        W4 o4 = pipe_step(s2, y2, SAFE ? true : (colin && (r + 1 < H)));

        if (wr) {
            float2 oa = __half22float2(o4.lo);
            float2 ob = __half22float2(o4.hi);
            if (z < NB) {
                float4 tv = *(const float4*)(tb + off);
                float4 pv = *(const float4*)(pb + off);
                s0  += oa.x * tv.x + oa.y * tv.y + ob.x * tv.z + ob.y * tv.w;
                s1a += oa.x + oa.y + ob.x + ob.y;
                s2a += pv.x * tv.x + pv.y * tv.y + pv.z * tv.z + pv.w * tv.w;
                s3  += pv.x + pv.y + pv.z + pv.w;
                s4  += tv.x + tv.y + tv.z + tv.w;
            } else {
                float4 pv = *(const float4*)(pb + off);
                s0  += oa.x * pv.x + oa.y * pv.y + ob.x * pv.z + ob.y * pv.w;
                s1a += oa.x + oa.y + ob.x + ob.y;
            }
        }
        off += W;
    }
}

__global__ void __launch_bounds__(256)
skel2_last(const float* __restrict__ pred, const float* __restrict__ target) {
    const int z = blockIdx.y;
    const __half* __restrict__ xp = g_B + (size_t)z * HW;
    const int b = (z < NB) ? z : z - NB;
    const float* __restrict__ pb = pred + (size_t)b * HW;
    const float* __restrict__ tb = target + (size_t)b * HW;

    const int lane = threadIdx.x & 31;
    const int warp = threadIdx.x >> 5;
    const int c0 = blockIdx.x * CPW - 4;
    const int gc = c0 + lane * 4;
    const bool colin = (gc >= 0) && (gc < W);
    const bool wr = (lane >= 1) && (lane <= 30) && colin;
    const int r0 = (blockIdx.z * WPB + warp) * RPW;
    const bool safe = (c0 >= 0) && (c0 + 128 <= W) &&
                      (r0 >= 4) && (r0 + RPW + 4 <= H);

    float s0 = 0, s1a = 0, s2a = 0, s3 = 0, s4 = 0;
    if (safe)
        skel_accum<true>(xp, pb, tb, z, r0, gc, colin, wr, s0, s1a, s2a, s3, s4);
    else
        skel_accum<false>(xp, pb, tb, z, r0, gc, colin, wr, s0, s1a, s2a, s3, s4);

    #pragma unroll
    for (int q = 16; q; q >>= 1) {
        s0  += __shfl_down_sync(0xffffffffu, s0, q);
        s1a += __shfl_down_sync(0xffffffffu, s1a, q);
        s2a += __shfl_down_sync(0xffffffffu, s2a, q);
        s3  += __shfl_down_sync(0xffffffffu, s3, q);
        s4  += __shfl_down_sync(0xffffffffu, s4, q);
    }
    __shared__ float sred[WPB][5];
    if (lane == 0) {
        sred[warp][0] = s0; sred[warp][1] = s1a; sred[warp][2] = s2a;
        sred[warp][3] = s3; sred[warp][4] = s4;
    }
    __syncthreads();
    if (threadIdx.x < 5) {
        float vv = 0;
        #pragma unroll
        for (int w = 0; w < WPB; w++) vv += sred[w][threadIdx.x];
        int q = threadIdx.x;
        if (z < NB) {
            int base = (q == 0) ? 0 : (q == 1) ? 64 : (q == 2) ? 256 : (q == 3) ? 320 : 384;
            atomicAdd(&g_acc[base + b], vv);
        } else if (q < 2) {
            atomicAdd(&g_acc[(q == 0 ? 128 : 192) + b], vv);
        }
    }
}

// ---------------------------------------------------------------------------
__global__ void zero_acc() {
    int i = threadIdx.x;
    if (i < 448) g_acc[i] = 0.0f;
}

__global__ void finalize_kernel(float* __restrict__ out) {
    int b = threadIdx.x;  // 64 threads
    float ifl = (g_acc[b] + 1.0f) / (g_acc[64 + b] + 1.0f);
    float tfl = (g_acc[128 + b] + 1.0f) / (g_acc[192 + b] + 1.0f);
    float it = ifl * tfl;
    float s  = ifl + tfl;
    float pt = g_acc[256 + b];
    float sp = g_acc[320 + b];
    float st = g_acc[384 + b];
    #pragma unroll
    for (int o = 16; o; o >>= 1) {
        it += __shfl_down_sync(0xffffffffu, it, o);
        s  += __shfl_down_sync(0xffffffffu, s,  o);
        pt += __shfl_down_sync(0xffffffffu, pt, o);
        sp += __shfl_down_sync(0xffffffffu, sp, o);
        st += __shfl_down_sync(0xffffffffu, st, o);
    }
    __shared__ float sh[5][2];
    if ((threadIdx.x & 31) == 0) {
        int w = threadIdx.x >> 5;
        sh[0][w] = it; sh[1][w] = s; sh[2][w] = pt; sh[3][w] = sp; sh[4][w] = st;
    }
    __syncthreads();
    if (threadIdx.x == 0) {
        float IT = sh[0][0] + sh[0][1];
        float S  = sh[1][0] + sh[1][1];
        float I  = sh[2][0] + sh[2][1];
        float Sp = sh[3][0] + sh[3][1];
        float St = sh[4][0] + sh[4][1];
        float dice   = 1.0f - (2.0f * I + 1e-6f) / (Sp + St + 1e-6f);
        float cldice = 1.0f - 2.0f * IT / S;
        out[0] = 0.8f * dice + 0.2f * cldice;
    }
}

// ---------------------------------------------------------------------------
extern "C" void kernel_launch(void* const* d_in, const int* in_sizes, int n_in,
                              void* d_out, int out_size) {
    const float* pred   = (const float*)d_in[0];
    const float* target = (const float*)d_in[1];
    float* out = (float*)d_out;

    zero_acc<<<1, 448>>>();

    dim3 blk(256);
    dim3 grd(NSTRIP, NZ, NRG);  // 5 x 128 x 2 = 1280 blocks

    skel2<<<grd, blk>>>(0, pred, target);   // iters 1-2: inputs -> A
    skel2<<<grd, blk>>>(1, pred, target);   // iters 3-4: A -> B
    skel2<<<grd, blk>>>(2, pred, target);   // iters 5-6: B -> A
    skel2<<<grd, blk>>>(1, pred, target);   // iters 7-8: A -> B
    skel2_last<<<grd, blk>>>(pred, target); // iters 9-10 + reductions (reads B)

    finalize_kernel<<<1, 64>>>(out);
}

// round 12
// speedup vs baseline: 1.0604x; 1.0604x over previous
#include <cuda_runtime.h>
#include <cuda_fp16.h>
#include <math_constants.h>
#include <cstdint>

#define H 512
#define W 512
#define NB 64
#define HW (H * W)
#define NZ (2 * NB)
#define CPW 120             // valid output columns per warp strip
#define NSTRIP 5            // ceil(512/120)
#define RPW 32              // output rows per warp
#define WPB 8               // warps per block
#define NRG 2               // row groups: 2*8*32 = 512 rows

#define FINF CUDART_INF_F

typedef unsigned int u32;

// Ping-pong fp16 buffers (67 MB each). Referenced ONLY from device code.
__device__ __half g_A[(size_t)NZ * HW];
__device__ __half g_B[(size_t)NZ * HW];
// [0..63] clp*t | [64..127] clp | [128..191] ts*p | [192..255] ts
// [256..319] p*t | [320..383] p | [384..447] t   (per-batch)
__device__ float g_acc[448];

__device__ __forceinline__ u32 h2u(__half2 v) { return *(u32*)&v; }
__device__ __forceinline__ __half2 u2h(u32 u) { return *(__half2*)&u; }

// 4 packed columns per lane: lo = (c0,c1), hi = (c2,c3)
struct W4 { __half2 lo, hi; };

__device__ __forceinline__ W4 bcast4(float f) {
    W4 w; w.lo = __float2half2_rn(f); w.hi = w.lo; return w;
}
__device__ __forceinline__ W4 inf4()  { return bcast4(FINF); }
__device__ __forceinline__ W4 ninf4() { return bcast4(-FINF); }

__device__ __forceinline__ W4 min3w(const W4& a, const W4& b, const W4& c) {
    W4 r;
    r.lo = __hmin2(a.lo, __hmin2(b.lo, c.lo));
    r.hi = __hmin2(a.hi, __hmin2(b.hi, c.hi));
    return r;
}
__device__ __forceinline__ W4 max3w(const W4& a, const W4& b, const W4& c) {
    W4 r;
    r.lo = __hmax2(a.lo, __hmax2(b.lo, c.lo));
    r.hi = __hmax2(a.hi, __hmax2(b.hi, c.hi));
    return r;
}

// Horizontal 3-window min/max over 4 packed cols; warp-edge lanes garbage
// (shfl wrap) — discarded via the validity margin.
__device__ __forceinline__ W4 hmin4(const W4& v) {
    u32 ulo = h2u(v.lo), uhi = h2u(v.hi);
    u32 lhi = __shfl_up_sync(0xffffffffu, uhi, 1);    // left lane's (c2,c3)
    u32 rlo = __shfl_down_sync(0xffffffffu, ulo, 1);  // right lane's (c0,c1)
    __half2 mid = u2h(__byte_perm(ulo, uhi, 0x5432)); // (x1, x2)
    __half2 shl = u2h(__byte_perm(lhi, ulo, 0x5432)); // (x-1, x0)
    __half2 shr = u2h(__byte_perm(uhi, rlo, 0x5432)); // (x3, x4)
    W4 h;
    h.lo = __hmin2(shl, __hmin2(v.lo, mid));
    h.hi = __hmin2(mid, __hmin2(v.hi, shr));
    return h;
}
__device__ __forceinline__ W4 hmax4(const W4& v) {
    u32 ulo = h2u(v.lo), uhi = h2u(v.hi);
    u32 lhi = __shfl_up_sync(0xffffffffu, uhi, 1);
    u32 rlo = __shfl_down_sync(0xffffffffu, ulo, 1);
    __half2 mid = u2h(__byte_perm(ulo, uhi, 0x5432));
    __half2 shl = u2h(__byte_perm(lhi, ulo, 0x5432));
    __half2 shr = u2h(__byte_perm(uhi, rlo, 0x5432));
    W4 h;
    h.lo = __hmax2(shl, __hmax2(v.lo, mid));
    h.hi = __hmax2(mid, __hmax2(v.hi, shr));
    return h;
}

// Rolling soft-skeletonize pipeline (one iteration stage), vertical-first max.
// At base row rb: next step consumes input row rb+2, emits output row rb.
// State: 6 W4 = 12 regs.
struct Pipe {
    W4 q0, q1;    // input rows rb, rb+1
    W4 hm0, hm1;  // horiz 3-min rows rb, rb+1
    W4 mpm, mp0;  // 3x3 min-pool rows rb-1, rb (-inf outside image)
};

__device__ __forceinline__ void pipe_init(Pipe& s, const W4& va, const W4& vb,
                                          const W4& vc, const W4& vd,
                                          bool okm, bool ok0) {
    W4 ha = hmin4(va), hb = hmin4(vb), hc = hmin4(vc), hd = hmin4(vd);
    s.mpm = okm ? min3w(ha, hb, hc) : ninf4();
    s.mp0 = ok0 ? min3w(hb, hc, hd) : ninf4();
    s.hm0 = hc; s.hm1 = hd; s.q0 = vc; s.q1 = vd;
}

// Advance one row: consume input row rb+2 (+inf-masked if invalid),
// okp1 = (row rb+1 in image) && colin. Emits output row rb.
// contour = hmax4(vertmax3(mp)) - mp0  (relu-free: window contains center).
__device__ __forceinline__ W4 pipe_step(Pipe& s, const W4& vin, bool okp1) {
    W4 hmn = hmin4(vin);
    W4 mpn = okp1 ? min3w(s.hm0, s.hm1, hmn) : ninf4();
    W4 vm = max3w(s.mpm, s.mp0, mpn);
    W4 hx = hmax4(vm);
    __half2 z = __float2half2_rn(0.0f);
    W4 o;
    o.lo = __hmax2(__hsub2(s.q0.lo, __hsub2(hx.lo, s.mp0.lo)), z);
    o.hi = __hmax2(__hsub2(s.q0.hi, __hsub2(hx.hi, s.mp0.hi)), z);
    s.mpm = s.mp0; s.mp0 = mpn;
    s.hm0 = s.hm1; s.hm1 = hmn;
    s.q0 = s.q1; s.q1 = vin;
    return o;
}

// fp16 source load (middle/last kernels): 8B per lane
__device__ __forceinline__ W4 ldh4(const __half* __restrict__ p, int r,
                                   int gc, bool colin) {
    if (colin && (unsigned)r < (unsigned)H) {
        uint2 t = *(const uint2*)(p + (size_t)r * W + gc);
        W4 w; w.lo = u2h(t.x); w.hi = u2h(t.y); return w;
    }
    return inf4();
}
// fp32 source load + convert (first kernel): 16B per lane
__device__ __forceinline__ W4 ldf4(const float* __restrict__ p, int r,
                                   int gc, bool colin) {
    if (colin && (unsigned)r < (unsigned)H) {
        float4 f = *(const float4*)(p + (size_t)r * W + gc);
        W4 w; w.lo = __floats2half2_rn(f.x, f.y);
        w.hi = __floats2half2_rn(f.z, f.w); return w;
    }
    return inf4();
}

// Prime both stages so the main loop at row r emits out2(r).
template <typename LD>
__device__ __forceinline__ void fused_prime(LD ld, Pipe& s1, Pipe& s2,
                                            int r0, bool colin) {
    pipe_init(s1, ld(r0 - 4), ld(r0 - 3), ld(r0 - 2), ld(r0 - 1),
              colin && (r0 - 3 >= 0), colin && (r0 - 2 >= 0));
    W4 ya = pipe_step(s1, ld(r0),     colin && (r0 - 1 >= 0));
    W4 yb = pipe_step(s1, ld(r0 + 1), colin);
    W4 yc = pipe_step(s1, ld(r0 + 2), colin);
    W4 yd = pipe_step(s1, ld(r0 + 3), colin);
    if (!colin || r0 - 2 < 0) ya = inf4();
    if (!colin || r0 - 1 < 0) yb = inf4();
    if (!colin) { yc = inf4(); yd = inf4(); }
    pipe_init(s2, ya, yb, yc, yd, colin && (r0 - 1 >= 0), colin);
}

// ---------------------------------------------------------------------------
// Two fused soft-skeletonize iterations per launch.
// mode 0: fp32 inputs -> g_A;  mode 1: g_A -> g_B;  mode 2: g_B -> g_A
// ---------------------------------------------------------------------------
__global__ void __launch_bounds__(256, 5)
skel2(int mode, const float* __restrict__ pred,
      const float* __restrict__ target) {
    const int z = blockIdx.y;
    const int lane = threadIdx.x & 31;
    const int warp = threadIdx.x >> 5;
    const int c0 = blockIdx.x * CPW - 4;
    const int gc = c0 + lane * 4;
    const bool colin = (gc >= 0) && (gc < W);   // 4-col group fully in/out
    const bool wr = (lane >= 1) && (lane <= 30) && colin;
    const int r0 = (blockIdx.z * WPB + warp) * RPW;

    const float* __restrict__ xf = nullptr;
    const __half* __restrict__ xh = nullptr;
    __half* __restrict__ op;
    if (mode == 0) {
        xf = (z < NB) ? pred + (size_t)z * HW : target + (size_t)(z - NB) * HW;
        op = g_A + (size_t)z * HW;
    } else if (mode == 1) {
        xh = g_A + (size_t)z * HW; op = g_B + (size_t)z * HW;
    } else {
        xh = g_B + (size_t)z * HW; op = g_A + (size_t)z * HW;
    }

    Pipe s1, s2;
    size_t off = (size_t)r0 * W + gc;

    if (mode == 0) {
        auto ld = [&](int r) { return ldf4(xf, r, gc, colin); };
        fused_prime(ld, s1, s2, r0, colin);
        #pragma unroll 4
        for (int r = r0; r < r0 + RPW; ++r) {
            W4 y2 = pipe_step(s1, ld(r + 4), colin && (r + 3 < H));
            if (!colin || (r + 2 >= H)) y2 = inf4();
            W4 o = pipe_step(s2, y2, colin && (r + 1 < H));
            if (wr) {
                uint2 st; st.x = h2u(o.lo); st.y = h2u(o.hi);
                *(uint2*)(op + off) = st;
            }
            off += W;
        }
    } else {
        auto ld = [&](int r) { return ldh4(xh, r, gc, colin); };
        fused_prime(ld, s1, s2, r0, colin);
        #pragma unroll 4
        for (int r = r0; r < r0 + RPW; ++r) {
            W4 y2 = pipe_step(s1, ld(r + 4), colin && (r + 3 < H));
            if (!colin || (r + 2 >= H)) y2 = inf4();
            W4 o = pipe_step(s2, y2, colin && (r + 1 < H));
            if (wr) {
                uint2 st; st.x = h2u(o.lo); st.y = h2u(o.hi);
                *(uint2*)(op + off) = st;
            }
            off += W;
        }
    }
}

// ---------------------------------------------------------------------------
// Final two iterations fused with all reductions (reads g_B, writes g_acc).
// ---------------------------------------------------------------------------
__global__ void __launch_bounds__(256)
skel2_last(const float* __restrict__ pred, const float* __restrict__ target) {
    const int z = blockIdx.y;
    const __half* __restrict__ xp = g_B + (size_t)z * HW;
    const int b = (z < NB) ? z : z - NB;
    const float* __restrict__ pb = pred + (size_t)b * HW;
    const float* __restrict__ tb = target + (size_t)b * HW;

    const int lane = threadIdx.x & 31;
    const int warp = threadIdx.x >> 5;
    const int c0 = blockIdx.x * CPW - 4;
    const int gc = c0 + lane * 4;
    const bool colin = (gc >= 0) && (gc < W);
    const bool wr = (lane >= 1) && (lane <= 30) && colin;
    const int r0 = (blockIdx.z * WPB + warp) * RPW;

    Pipe s1, s2;
    auto ld = [&](int r) { return ldh4(xp, r, gc, colin); };
    fused_prime(ld, s1, s2, r0, colin);

    float s0 = 0, s1a = 0, s2a = 0, s3 = 0, s4 = 0;

    size_t off = (size_t)r0 * W + gc;
    #pragma unroll 4
    for (int r = r0; r < r0 + RPW; ++r) {
        W4 y2 = pipe_step(s1, ld(r + 4), colin && (r + 3 < H));
        if (!colin || (r + 2 >= H)) y2 = inf4();
        W4 o4 = pipe_step(s2, y2, colin && (r + 1 < H));

        if (wr) {
            float2 oa = __half22float2(o4.lo);
            float2 ob = __half22float2(o4.hi);
            if (z < NB) {   // o = cl_pred pixels; also dice terms (exact fp32)
                float4 tv = *(const float4*)(tb + off);
                float4 pv = *(const float4*)(pb + off);
                s0  += oa.x * tv.x + oa.y * tv.y + ob.x * tv.z + ob.y * tv.w;
                s1a += oa.x + oa.y + ob.x + ob.y;
                s2a += pv.x * tv.x + pv.y * tv.y + pv.z * tv.z + pv.w * tv.w;
                s3  += pv.x + pv.y + pv.z + pv.w;
                s4  += tv.x + tv.y + tv.z + tv.w;
            } else {        // o = target_skeleton pixels
                float4 pv = *(const float4*)(pb + off);
                s0  += oa.x * pv.x + oa.y * pv.y + ob.x * pv.z + ob.y * pv.w;
                s1a += oa.x + oa.y + ob.x + ob.y;
            }
        }
        off += W;
    }

    #pragma unroll
    for (int q = 16; q; q >>= 1) {
        s0  += __shfl_down_sync(0xffffffffu, s0, q);
        s1a += __shfl_down_sync(0xffffffffu, s1a, q);
        s2a += __shfl_down_sync(0xffffffffu, s2a, q);
        s3  += __shfl_down_sync(0xffffffffu, s3, q);
        s4  += __shfl_down_sync(0xffffffffu, s4, q);
    }
    __shared__ float sred[WPB][5];
    if (lane == 0) {
        sred[warp][0] = s0; sred[warp][1] = s1a; sred[warp][2] = s2a;
        sred[warp][3] = s3; sred[warp][4] = s4;
    }
    __syncthreads();
    if (threadIdx.x < 5) {
        float vv = 0;
        #pragma unroll
        for (int w = 0; w < WPB; w++) vv += sred[w][threadIdx.x];
        int q = threadIdx.x;
        if (z < NB) {
            int base = (q == 0) ? 0 : (q == 1) ? 64 : (q == 2) ? 256 : (q == 3) ? 320 : 384;
            atomicAdd(&g_acc[base + b], vv);
        } else if (q < 2) {
            atomicAdd(&g_acc[(q == 0 ? 128 : 192) + b], vv);
        }
    }
}

// ---------------------------------------------------------------------------
__global__ void zero_acc() {
    int i = threadIdx.x;
    if (i < 448) g_acc[i] = 0.0f;
}

__global__ void finalize_kernel(float* __restrict__ out) {
    int b = threadIdx.x;  // 64 threads
    float ifl = (g_acc[b] + 1.0f) / (g_acc[64 + b] + 1.0f);
    float tfl = (g_acc[128 + b] + 1.0f) / (g_acc[192 + b] + 1.0f);
    float it = ifl * tfl;
    float s  = ifl + tfl;
    float pt = g_acc[256 + b];
    float sp = g_acc[320 + b];
    float st = g_acc[384 + b];
    #pragma unroll
    for (int o = 16; o; o >>= 1) {
        it += __shfl_down_sync(0xffffffffu, it, o);
        s  += __shfl_down_sync(0xffffffffu, s,  o);
        pt += __shfl_down_sync(0xffffffffu, pt, o);
        sp += __shfl_down_sync(0xffffffffu, sp, o);
        st += __shfl_down_sync(0xffffffffu, st, o);
    }
    __shared__ float sh[5][2];
    if ((threadIdx.x & 31) == 0) {
        int w = threadIdx.x >> 5;
        sh[0][w] = it; sh[1][w] = s; sh[2][w] = pt; sh[3][w] = sp; sh[4][w] = st;
    }
    __syncthreads();
    if (threadIdx.x == 0) {
        float IT = sh[0][0] + sh[0][1];
        float S  = sh[1][0] + sh[1][1];
        float I  = sh[2][0] + sh[2][1];
        float Sp = sh[3][0] + sh[3][1];
        float St = sh[4][0] + sh[4][1];
        float dice   = 1.0f - (2.0f * I + 1e-6f) / (Sp + St + 1e-6f);
        float cldice = 1.0f - 2.0f * IT / S;
        out[0] = 0.8f * dice + 0.2f * cldice;
    }
}

// ---------------------------------------------------------------------------
extern "C" void kernel_launch(void* const* d_in, const int* in_sizes, int n_in,
                              void* d_out, int out_size) {
    const float* pred   = (const float*)d_in[0];
    const float* target = (const float*)d_in[1];
    float* out = (float*)d_out;

    zero_acc<<<1, 448>>>();

    dim3 blk(256);
    dim3 grd(NSTRIP, NZ, NRG);  // 5 x 128 x 2 = 1280 blocks

    skel2<<<grd, blk>>>(0, pred, target);   // iters 1-2: inputs -> A
    skel2<<<grd, blk>>>(1, pred, target);   // iters 3-4: A -> B
    skel2<<<grd, blk>>>(2, pred, target);   // iters 5-6: B -> A
    skel2<<<grd, blk>>>(1, pred, target);   // iters 7-8: A -> B
    skel2_last<<<grd, blk>>>(pred, target); // iters 9-10 + reductions (reads B)

    finalize_kernel<<<1, 64>>>(out);
}

// round 13
// speedup vs baseline: 1.0849x; 1.0231x over previous
#include <cuda_runtime.h>
#include <cuda_fp16.h>
#include <math_constants.h>
#include <cstdint>

#define H 512
#define W 512
#define NB 64
#define HW (H * W)
#define NZ (2 * NB)
#define CPW 120             // valid output columns per warp strip
#define NSTRIP 5            // ceil(512/120)
#define RPW 64              // output rows per warp
#define WPB 4               // warps per block (128 threads)
#define NRG 2               // row groups: 2*4*64 = 512 rows

#define FINF CUDART_INF_F

typedef unsigned int u32;

// Ping-pong fp16 buffers (67 MB each). Referenced ONLY from device code.
__device__ __half g_A[(size_t)NZ * HW];
__device__ __half g_B[(size_t)NZ * HW];
// [0..63] clp*t | [64..127] clp | [128..191] ts*p | [192..255] ts
// [256..319] p*t | [320..383] p | [384..447] t   (per-batch)
__device__ float g_acc[448];

__device__ __forceinline__ u32 h2u(__half2 v) { return *(u32*)&v; }
__device__ __forceinline__ __half2 u2h(u32 u) { return *(__half2*)&u; }

// 4 packed columns per lane: lo = (c0,c1), hi = (c2,c3)
struct W4 { __half2 lo, hi; };

__device__ __forceinline__ W4 bcast4(float f) {
    W4 w; w.lo = __float2half2_rn(f); w.hi = w.lo; return w;
}
__device__ __forceinline__ W4 inf4()  { return bcast4(FINF); }
__device__ __forceinline__ W4 ninf4() { return bcast4(-FINF); }

__device__ __forceinline__ W4 min3w(const W4& a, const W4& b, const W4& c) {
    W4 r;
    r.lo = __hmin2(a.lo, __hmin2(b.lo, c.lo));
    r.hi = __hmin2(a.hi, __hmin2(b.hi, c.hi));
    return r;
}
__device__ __forceinline__ W4 max3w(const W4& a, const W4& b, const W4& c) {
    W4 r;
    r.lo = __hmax2(a.lo, __hmax2(b.lo, c.lo));
    r.hi = __hmax2(a.hi, __hmax2(b.hi, c.hi));
    return r;
}

// Horizontal 3-window min/max over 4 packed cols; warp-edge lanes garbage
// (shfl wrap) — discarded via the validity margin.
__device__ __forceinline__ W4 hmin4(const W4& v) {
    u32 ulo = h2u(v.lo), uhi = h2u(v.hi);
    u32 lhi = __shfl_up_sync(0xffffffffu, uhi, 1);    // left lane's (c2,c3)
    u32 rlo = __shfl_down_sync(0xffffffffu, ulo, 1);  // right lane's (c0,c1)
    __half2 mid = u2h(__byte_perm(ulo, uhi, 0x5432)); // (x1, x2)
    __half2 shl = u2h(__byte_perm(lhi, ulo, 0x5432)); // (x-1, x0)
    __half2 shr = u2h(__byte_perm(uhi, rlo, 0x5432)); // (x3, x4)
    W4 h;
    h.lo = __hmin2(shl, __hmin2(v.lo, mid));
    h.hi = __hmin2(mid, __hmin2(v.hi, shr));
    return h;
}
__device__ __forceinline__ W4 hmax4(const W4& v) {
    u32 ulo = h2u(v.lo), uhi = h2u(v.hi);
    u32 lhi = __shfl_up_sync(0xffffffffu, uhi, 1);
    u32 rlo = __shfl_down_sync(0xffffffffu, ulo, 1);
    __half2 mid = u2h(__byte_perm(ulo, uhi, 0x5432));
    __half2 shl = u2h(__byte_perm(lhi, ulo, 0x5432));
    __half2 shr = u2h(__byte_perm(uhi, rlo, 0x5432));
    W4 h;
    h.lo = __hmax2(shl, __hmax2(v.lo, mid));
    h.hi = __hmax2(mid, __hmax2(v.hi, shr));
    return h;
}

// Rolling soft-skeletonize pipeline (one iteration stage), vertical-first max.
// At base row rb: next step consumes input row rb+2, emits output row rb.
// State: 6 W4 = 12 regs.
struct Pipe {
    W4 q0, q1;    // input rows rb, rb+1
    W4 hm0, hm1;  // horiz 3-min rows rb, rb+1
    W4 mpm, mp0;  // 3x3 min-pool rows rb-1, rb (-inf outside image)
};

__device__ __forceinline__ void pipe_init(Pipe& s, const W4& va, const W4& vb,
                                          const W4& vc, const W4& vd,
                                          bool okm, bool ok0) {
    W4 ha = hmin4(va), hb = hmin4(vb), hc = hmin4(vc), hd = hmin4(vd);
    s.mpm = okm ? min3w(ha, hb, hc) : ninf4();
    s.mp0 = ok0 ? min3w(hb, hc, hd) : ninf4();
    s.hm0 = hc; s.hm1 = hd; s.q0 = vc; s.q1 = vd;
}

// Advance one row: consume input row rb+2 (+inf-masked if invalid),
// okp1 = (row rb+1 in image) && colin. Emits output row rb.
// contour = hmax4(vertmax3(mp)) - mp0  (relu-free: window contains center).
__device__ __forceinline__ W4 pipe_step(Pipe& s, const W4& vin, bool okp1) {
    W4 hmn = hmin4(vin);
    W4 mpn = okp1 ? min3w(s.hm0, s.hm1, hmn) : ninf4();
    W4 vm = max3w(s.mpm, s.mp0, mpn);
    W4 hx = hmax4(vm);
    __half2 z = __float2half2_rn(0.0f);
    W4 o;
    o.lo = __hmax2(__hsub2(s.q0.lo, __hsub2(hx.lo, s.mp0.lo)), z);
    o.hi = __hmax2(__hsub2(s.q0.hi, __hsub2(hx.hi, s.mp0.hi)), z);
    s.mpm = s.mp0; s.mp0 = mpn;
    s.hm0 = s.hm1; s.hm1 = hmn;
    s.q0 = s.q1; s.q1 = vin;
    return o;
}

// fp16 source load (middle/last kernels): 8B per lane
__device__ __forceinline__ W4 ldh4(const __half* __restrict__ p, int r,
                                   int gc, bool colin) {
    if (colin && (unsigned)r < (unsigned)H) {
        uint2 t = *(const uint2*)(p + (size_t)r * W + gc);
        W4 w; w.lo = u2h(t.x); w.hi = u2h(t.y); return w;
    }
    return inf4();
}
// fp32 source load + convert (first kernel): 16B per lane
__device__ __forceinline__ W4 ldf4(const float* __restrict__ p, int r,
                                   int gc, bool colin) {
    if (colin && (unsigned)r < (unsigned)H) {
        float4 f = *(const float4*)(p + (size_t)r * W + gc);
        W4 w; w.lo = __floats2half2_rn(f.x, f.y);
        w.hi = __floats2half2_rn(f.z, f.w); return w;
    }
    return inf4();
}

// Prime both stages so the main loop at row r emits out2(r).
template <typename LD>
__device__ __forceinline__ void fused_prime(LD ld, Pipe& s1, Pipe& s2,
                                            int r0, bool colin) {
    pipe_init(s1, ld(r0 - 4), ld(r0 - 3), ld(r0 - 2), ld(r0 - 1),
              colin && (r0 - 3 >= 0), colin && (r0 - 2 >= 0));
    W4 ya = pipe_step(s1, ld(r0),     colin && (r0 - 1 >= 0));
    W4 yb = pipe_step(s1, ld(r0 + 1), colin);
    W4 yc = pipe_step(s1, ld(r0 + 2), colin);
    W4 yd = pipe_step(s1, ld(r0 + 3), colin);
    if (!colin || r0 - 2 < 0) ya = inf4();
    if (!colin || r0 - 1 < 0) yb = inf4();
    if (!colin) { yc = inf4(); yd = inf4(); }
    pipe_init(s2, ya, yb, yc, yd, colin && (r0 - 1 >= 0), colin);
}

// ---------------------------------------------------------------------------
// Two fused soft-skeletonize iterations per launch.
// mode 0: fp32 inputs -> g_A;  mode 1: g_A -> g_B;  mode 2: g_B -> g_A
// ---------------------------------------------------------------------------
__global__ void __launch_bounds__(128, 10)
skel2(int mode, const float* __restrict__ pred,
      const float* __restrict__ target) {
    const int z = blockIdx.y;
    const int lane = threadIdx.x & 31;
    const int warp = threadIdx.x >> 5;
    const int c0 = blockIdx.x * CPW - 4;
    const int gc = c0 + lane * 4;
    const bool colin = (gc >= 0) && (gc < W);   // 4-col group fully in/out
    const bool wr = (lane >= 1) && (lane <= 30) && colin;
    const int r0 = (blockIdx.z * WPB + warp) * RPW;

    const float* __restrict__ xf = nullptr;
    const __half* __restrict__ xh = nullptr;
    __half* __restrict__ op;
    if (mode == 0) {
        xf = (z < NB) ? pred + (size_t)z * HW : target + (size_t)(z - NB) * HW;
        op = g_A + (size_t)z * HW;
    } else if (mode == 1) {
        xh = g_A + (size_t)z * HW; op = g_B + (size_t)z * HW;
    } else {
        xh = g_B + (size_t)z * HW; op = g_A + (size_t)z * HW;
    }

    Pipe s1, s2;
    size_t off = (size_t)r0 * W + gc;

    if (mode == 0) {
        auto ld = [&](int r) { return ldf4(xf, r, gc, colin); };
        fused_prime(ld, s1, s2, r0, colin);
        #pragma unroll 4
        for (int r = r0; r < r0 + RPW; ++r) {
            W4 y2 = pipe_step(s1, ld(r + 4), colin && (r + 3 < H));
            if (!colin || (r + 2 >= H)) y2 = inf4();
            W4 o = pipe_step(s2, y2, colin && (r + 1 < H));
            if (wr) {
                uint2 st; st.x = h2u(o.lo); st.y = h2u(o.hi);
                *(uint2*)(op + off) = st;
            }
            off += W;
        }
    } else {
        auto ld = [&](int r) { return ldh4(xh, r, gc, colin); };
        fused_prime(ld, s1, s2, r0, colin);
        #pragma unroll 4
        for (int r = r0; r < r0 + RPW; ++r) {
            W4 y2 = pipe_step(s1, ld(r + 4), colin && (r + 3 < H));
            if (!colin || (r + 2 >= H)) y2 = inf4();
            W4 o = pipe_step(s2, y2, colin && (r + 1 < H));
            if (wr) {
                uint2 st; st.x = h2u(o.lo); st.y = h2u(o.hi);
                *(uint2*)(op + off) = st;
            }
            off += W;
        }
    }
}

// ---------------------------------------------------------------------------
// Final two iterations fused with all reductions (reads g_B, writes g_acc).
// ---------------------------------------------------------------------------
__global__ void __launch_bounds__(128, 10)
skel2_last(const float* __restrict__ pred, const float* __restrict__ target) {
    const int z = blockIdx.y;
    const __half* __restrict__ xp = g_B + (size_t)z * HW;
    const int b = (z < NB) ? z : z - NB;
    const float* __restrict__ pb = pred + (size_t)b * HW;
    const float* __restrict__ tb = target + (size_t)b * HW;

    const int lane = threadIdx.x & 31;
    const int warp = threadIdx.x >> 5;
    const int c0 = blockIdx.x * CPW - 4;
    const int gc = c0 + lane * 4;
    const bool colin = (gc >= 0) && (gc < W);
    const bool wr = (lane >= 1) && (lane <= 30) && colin;
    const int r0 = (blockIdx.z * WPB + warp) * RPW;

    Pipe s1, s2;
    auto ld = [&](int r) { return ldh4(xp, r, gc, colin); };
    fused_prime(ld, s1, s2, r0, colin);

    float s0 = 0, s1a = 0, s2a = 0, s3 = 0, s4 = 0;

    size_t off = (size_t)r0 * W + gc;
    #pragma unroll 4
    for (int r = r0; r < r0 + RPW; ++r) {
        W4 y2 = pipe_step(s1, ld(r + 4), colin && (r + 3 < H));
        if (!colin || (r + 2 >= H)) y2 = inf4();
        W4 o4 = pipe_step(s2, y2, colin && (r + 1 < H));

        if (wr) {
            float2 oa = __half22float2(o4.lo);
            float2 ob = __half22float2(o4.hi);
            if (z < NB) {   // o = cl_pred pixels; also dice terms (exact fp32)
                float4 tv = *(const float4*)(tb + off);
                float4 pv = *(const float4*)(pb + off);
                s0  += oa.x * tv.x + oa.y * tv.y + ob.x * tv.z + ob.y * tv.w;
                s1a += oa.x + oa.y + ob.x + ob.y;
                s2a += pv.x * tv.x + pv.y * tv.y + pv.z * tv.z + pv.w * tv.w;
                s3  += pv.x + pv.y + pv.z + pv.w;
                s4  += tv.x + tv.y + tv.z + tv.w;
            } else {        // o = target_skeleton pixels
                float4 pv = *(const float4*)(pb + off);
                s0  += oa.x * pv.x + oa.y * pv.y + ob.x * pv.z + ob.y * pv.w;
                s1a += oa.x + oa.y + ob.x + ob.y;
            }
        }
        off += W;
    }

    #pragma unroll
    for (int q = 16; q; q >>= 1) {
        s0  += __shfl_down_sync(0xffffffffu, s0, q);
        s1a += __shfl_down_sync(0xffffffffu, s1a, q);
        s2a += __shfl_down_sync(0xffffffffu, s2a, q);
        s3  += __shfl_down_sync(0xffffffffu, s3, q);
        s4  += __shfl_down_sync(0xffffffffu, s4, q);
    }
    __shared__ float sred[WPB][5];
    if (lane == 0) {
        sred[warp][0] = s0; sred[warp][1] = s1a; sred[warp][2] = s2a;
        sred[warp][3] = s3; sred[warp][4] = s4;
    }
    __syncthreads();
    if (threadIdx.x < 5) {
        float vv = 0;
        #pragma unroll
        for (int w = 0; w < WPB; w++) vv += sred[w][threadIdx.x];
        int q = threadIdx.x;
        if (z < NB) {
            int base = (q == 0) ? 0 : (q == 1) ? 64 : (q == 2) ? 256 : (q == 3) ? 320 : 384;
            atomicAdd(&g_acc[base + b], vv);
        } else if (q < 2) {
            atomicAdd(&g_acc[(q == 0 ? 128 : 192) + b], vv);
        }
    }
}

// ---------------------------------------------------------------------------
__global__ void zero_acc() {
    int i = threadIdx.x;
    if (i < 448) g_acc[i] = 0.0f;
}

__global__ void finalize_kernel(float* __restrict__ out) {
    int b = threadIdx.x;  // 64 threads
    float ifl = (g_acc[b] + 1.0f) / (g_acc[64 + b] + 1.0f);
    float tfl = (g_acc[128 + b] + 1.0f) / (g_acc[192 + b] + 1.0f);
    float it = ifl * tfl;
    float s  = ifl + tfl;
    float pt = g_acc[256 + b];
    float sp = g_acc[320 + b];
    float st = g_acc[384 + b];
    #pragma unroll
    for (int o = 16; o; o >>= 1) {
        it += __shfl_down_sync(0xffffffffu, it, o);
        s  += __shfl_down_sync(0xffffffffu, s,  o);
        pt += __shfl_down_sync(0xffffffffu, pt, o);
        sp += __shfl_down_sync(0xffffffffu, sp, o);
        st += __shfl_down_sync(0xffffffffu, st, o);
    }
    __shared__ float sh[5][2];
    if ((threadIdx.x & 31) == 0) {
        int w = threadIdx.x >> 5;
        sh[0][w] = it; sh[1][w] = s; sh[2][w] = pt; sh[3][w] = sp; sh[4][w] = st;
    }
    __syncthreads();
    if (threadIdx.x == 0) {
        float IT = sh[0][0] + sh[0][1];
        float S  = sh[1][0] + sh[1][1];
        float I  = sh[2][0] + sh[2][1];
        float Sp = sh[3][0] + sh[3][1];
        float St = sh[4][0] + sh[4][1];
        float dice   = 1.0f - (2.0f * I + 1e-6f) / (Sp + St + 1e-6f);
        float cldice = 1.0f - 2.0f * IT / S;
        out[0] = 0.8f * dice + 0.2f * cldice;
    }
}

// ---------------------------------------------------------------------------
extern "C" void kernel_launch(void* const* d_in, const int* in_sizes, int n_in,
                              void* d_out, int out_size) {
    const float* pred   = (const float*)d_in[0];
    const float* target = (const float*)d_in[1];
    float* out = (float*)d_out;

    zero_acc<<<1, 448>>>();

    dim3 blk(128);
    dim3 grd(NSTRIP, NZ, NRG);  // 5 x 128 x 2 = 1280 blocks (128 thr)

    skel2<<<grd, blk>>>(0, pred, target);   // iters 1-2: inputs -> A
    skel2<<<grd, blk>>>(1, pred, target);   // iters 3-4: A -> B
    skel2<<<grd, blk>>>(2, pred, target);   // iters 5-6: B -> A
    skel2<<<grd, blk>>>(1, pred, target);   // iters 7-8: A -> B
    skel2_last<<<grd, blk>>>(pred, target); // iters 9-10 + reductions (reads B)

    finalize_kernel<<<1, 64>>>(out);
}

// round 14
// speedup vs baseline: 1.1743x; 1.0824x over previous
#include <cuda_runtime.h>
#include <cuda_fp16.h>
#include <math_constants.h>
#include <cstdint>

#define H 512
#define W 512
#define NB 64
#define HW (H * W)
#define NZ (2 * NB)
#define CPW 120             // valid output columns per warp strip
#define NSTRIP 5            // ceil(512/120)
#define RPW 32              // output rows per warp
#define WPB 4               // warps per block (128 threads)
#define NRG 4               // row groups: 4*4*32 = 512 rows

#define FINF CUDART_INF_F

typedef unsigned int u32;

// Ping-pong fp16 buffers (67 MB each). Referenced ONLY from device code.
__device__ __half g_A[(size_t)NZ * HW];
__device__ __half g_B[(size_t)NZ * HW];
// [0..63] clp*t | [64..127] clp | [128..191] ts*p | [192..255] ts
// [256..319] p*t | [320..383] p | [384..447] t   (per-batch)
__device__ float g_acc[448];

__device__ __forceinline__ u32 h2u(__half2 v) { return *(u32*)&v; }
__device__ __forceinline__ __half2 u2h(u32 u) { return *(__half2*)&u; }

// 4 packed columns per lane: lo = (c0,c1), hi = (c2,c3)
struct W4 { __half2 lo, hi; };

__device__ __forceinline__ W4 bcast4(float f) {
    W4 w; w.lo = __float2half2_rn(f); w.hi = w.lo; return w;
}
__device__ __forceinline__ W4 inf4()  { return bcast4(FINF); }
__device__ __forceinline__ W4 ninf4() { return bcast4(-FINF); }

__device__ __forceinline__ W4 min3w(const W4& a, const W4& b, const W4& c) {
    W4 r;
    r.lo = __hmin2(a.lo, __hmin2(b.lo, c.lo));
    r.hi = __hmin2(a.hi, __hmin2(b.hi, c.hi));
    return r;
}
__device__ __forceinline__ W4 max3w(const W4& a, const W4& b, const W4& c) {
    W4 r;
    r.lo = __hmax2(a.lo, __hmax2(b.lo, c.lo));
    r.hi = __hmax2(a.hi, __hmax2(b.hi, c.hi));
    return r;
}

// Horizontal 3-window min/max over 4 packed cols; warp-edge lanes garbage
// (shfl wrap) — discarded via the validity margin.
__device__ __forceinline__ W4 hmin4(const W4& v) {
    u32 ulo = h2u(v.lo), uhi = h2u(v.hi);
    u32 lhi = __shfl_up_sync(0xffffffffu, uhi, 1);    // left lane's (c2,c3)
    u32 rlo = __shfl_down_sync(0xffffffffu, ulo, 1);  // right lane's (c0,c1)
    __half2 mid = u2h(__byte_perm(ulo, uhi, 0x5432)); // (x1, x2)
    __half2 shl = u2h(__byte_perm(lhi, ulo, 0x5432)); // (x-1, x0)
    __half2 shr = u2h(__byte_perm(uhi, rlo, 0x5432)); // (x3, x4)
    W4 h;
    h.lo = __hmin2(shl, __hmin2(v.lo, mid));
    h.hi = __hmin2(mid, __hmin2(v.hi, shr));
    return h;
}
__device__ __forceinline__ W4 hmax4(const W4& v) {
    u32 ulo = h2u(v.lo), uhi = h2u(v.hi);
    u32 lhi = __shfl_up_sync(0xffffffffu, uhi, 1);
    u32 rlo = __shfl_down_sync(0xffffffffu, ulo, 1);
    __half2 mid = u2h(__byte_perm(ulo, uhi, 0x5432));
    __half2 shl = u2h(__byte_perm(lhi, ulo, 0x5432));
    __half2 shr = u2h(__byte_perm(uhi, rlo, 0x5432));
    W4 h;
    h.lo = __hmax2(shl, __hmax2(v.lo, mid));
    h.hi = __hmax2(mid, __hmax2(v.hi, shr));
    return h;
}

// Rolling soft-skeletonize pipeline (one iteration stage), vertical-first max.
// At base row rb: next step consumes input row rb+2, emits output row rb.
// State: 6 W4 = 12 regs.
struct Pipe {
    W4 q0, q1;    // input rows rb, rb+1
    W4 hm0, hm1;  // horiz 3-min rows rb, rb+1
    W4 mpm, mp0;  // 3x3 min-pool rows rb-1, rb (-inf outside image)
};

__device__ __forceinline__ void pipe_init(Pipe& s, const W4& va, const W4& vb,
                                          const W4& vc, const W4& vd,
                                          bool okm, bool ok0) {
    W4 ha = hmin4(va), hb = hmin4(vb), hc = hmin4(vc), hd = hmin4(vd);
    s.mpm = okm ? min3w(ha, hb, hc) : ninf4();
    s.mp0 = ok0 ? min3w(hb, hc, hd) : ninf4();
    s.hm0 = hc; s.hm1 = hd; s.q0 = vc; s.q1 = vd;
}

// Advance one row: consume input row rb+2 (+inf-masked if invalid),
// okp1 = (row rb+1 in image) && colin. Emits output row rb.
// contour = hmax4(vertmax3(mp)) - mp0  (relu-free: window contains center).
__device__ __forceinline__ W4 pipe_step(Pipe& s, const W4& vin, bool okp1) {
    W4 hmn = hmin4(vin);
    W4 mpn = okp1 ? min3w(s.hm0, s.hm1, hmn) : ninf4();
    W4 vm = max3w(s.mpm, s.mp0, mpn);
    W4 hx = hmax4(vm);
    __half2 z = __float2half2_rn(0.0f);
    W4 o;
    o.lo = __hmax2(__hsub2(s.q0.lo, __hsub2(hx.lo, s.mp0.lo)), z);
    o.hi = __hmax2(__hsub2(s.q0.hi, __hsub2(hx.hi, s.mp0.hi)), z);
    s.mpm = s.mp0; s.mp0 = mpn;
    s.hm0 = s.hm1; s.hm1 = hmn;
    s.q0 = s.q1; s.q1 = vin;
    return o;
}

// fp16 source load (middle/last kernels): 8B per lane
__device__ __forceinline__ W4 ldh4(const __half* __restrict__ p, int r,
                                   int gc, bool colin) {
    if (colin && (unsigned)r < (unsigned)H) {
        uint2 t = *(const uint2*)(p + (size_t)r * W + gc);
        W4 w; w.lo = u2h(t.x); w.hi = u2h(t.y); return w;
    }
    return inf4();
}
// fp32 source load + convert (first kernel): 16B per lane
__device__ __forceinline__ W4 ldf4(const float* __restrict__ p, int r,
                                   int gc, bool colin) {
    if (colin && (unsigned)r < (unsigned)H) {
        float4 f = *(const float4*)(p + (size_t)r * W + gc);
        W4 w; w.lo = __floats2half2_rn(f.x, f.y);
        w.hi = __floats2half2_rn(f.z, f.w); return w;
    }
    return inf4();
}

// Prime both stages so the main loop at row r emits out2(r).
template <typename LD>
__device__ __forceinline__ void fused_prime(LD ld, Pipe& s1, Pipe& s2,
                                            int r0, bool colin) {
    pipe_init(s1, ld(r0 - 4), ld(r0 - 3), ld(r0 - 2), ld(r0 - 1),
              colin && (r0 - 3 >= 0), colin && (r0 - 2 >= 0));
    W4 ya = pipe_step(s1, ld(r0),     colin && (r0 - 1 >= 0));
    W4 yb = pipe_step(s1, ld(r0 + 1), colin);
    W4 yc = pipe_step(s1, ld(r0 + 2), colin);
    W4 yd = pipe_step(s1, ld(r0 + 3), colin);
    if (!colin || r0 - 2 < 0) ya = inf4();
    if (!colin || r0 - 1 < 0) yb = inf4();
    if (!colin) { yc = inf4(); yd = inf4(); }
    pipe_init(s2, ya, yb, yc, yd, colin && (r0 - 1 >= 0), colin);
}

// ---------------------------------------------------------------------------
// Two fused soft-skeletonize iterations per launch.
// mode 0: fp32 inputs -> g_A;  mode 1: g_A -> g_B;  mode 2: g_B -> g_A
// ---------------------------------------------------------------------------
__global__ void __launch_bounds__(128, 10)
skel2(int mode, const float* __restrict__ pred,
      const float* __restrict__ target) {
    const int z = blockIdx.y;
    const int lane = threadIdx.x & 31;
    const int warp = threadIdx.x >> 5;
    const int c0 = blockIdx.x * CPW - 4;
    const int gc = c0 + lane * 4;
    const bool colin = (gc >= 0) && (gc < W);   // 4-col group fully in/out
    const bool wr = (lane >= 1) && (lane <= 30) && colin;
    const int r0 = (blockIdx.z * WPB + warp) * RPW;

    const float* __restrict__ xf = nullptr;
    const __half* __restrict__ xh = nullptr;
    __half* __restrict__ op;
    if (mode == 0) {
        xf = (z < NB) ? pred + (size_t)z * HW : target + (size_t)(z - NB) * HW;
        op = g_A + (size_t)z * HW;
    } else if (mode == 1) {
        xh = g_A + (size_t)z * HW; op = g_B + (size_t)z * HW;
    } else {
        xh = g_B + (size_t)z * HW; op = g_A + (size_t)z * HW;
    }

    Pipe s1, s2;
    size_t off = (size_t)r0 * W + gc;

    if (mode == 0) {
        auto ld = [&](int r) { return ldf4(xf, r, gc, colin); };
        fused_prime(ld, s1, s2, r0, colin);
        #pragma unroll 4
        for (int r = r0; r < r0 + RPW; ++r) {
            W4 y2 = pipe_step(s1, ld(r + 4), colin && (r + 3 < H));
            if (!colin || (r + 2 >= H)) y2 = inf4();
            W4 o = pipe_step(s2, y2, colin && (r + 1 < H));
            if (wr) {
                uint2 st; st.x = h2u(o.lo); st.y = h2u(o.hi);
                *(uint2*)(op + off) = st;
            }
            off += W;
        }
    } else {
        auto ld = [&](int r) { return ldh4(xh, r, gc, colin); };
        fused_prime(ld, s1, s2, r0, colin);
        #pragma unroll 4
        for (int r = r0; r < r0 + RPW; ++r) {
            W4 y2 = pipe_step(s1, ld(r + 4), colin && (r + 3 < H));
            if (!colin || (r + 2 >= H)) y2 = inf4();
            W4 o = pipe_step(s2, y2, colin && (r + 1 < H));
            if (wr) {
                uint2 st; st.x = h2u(o.lo); st.y = h2u(o.hi);
                *(uint2*)(op + off) = st;
            }
            off += W;
        }
    }
}

// ---------------------------------------------------------------------------
// Final two iterations fused with all reductions (reads g_B, writes g_acc).
// ---------------------------------------------------------------------------
__global__ void __launch_bounds__(128, 10)
skel2_last(const float* __restrict__ pred, const float* __restrict__ target) {
    const int z = blockIdx.y;
    const __half* __restrict__ xp = g_B + (size_t)z * HW;
    const int b = (z < NB) ? z : z - NB;
    const float* __restrict__ pb = pred + (size_t)b * HW;
    const float* __restrict__ tb = target + (size_t)b * HW;

    const int lane = threadIdx.x & 31;
    const int warp = threadIdx.x >> 5;
    const int c0 = blockIdx.x * CPW - 4;
    const int gc = c0 + lane * 4;
    const bool colin = (gc >= 0) && (gc < W);
    const bool wr = (lane >= 1) && (lane <= 30) && colin;
    const int r0 = (blockIdx.z * WPB + warp) * RPW;

    Pipe s1, s2;
    auto ld = [&](int r) { return ldh4(xp, r, gc, colin); };
    fused_prime(ld, s1, s2, r0, colin);

    float s0 = 0, s1a = 0, s2a = 0, s3 = 0, s4 = 0;

    size_t off = (size_t)r0 * W + gc;
    #pragma unroll 4
    for (int r = r0; r < r0 + RPW; ++r) {
        W4 y2 = pipe_step(s1, ld(r + 4), colin && (r + 3 < H));
        if (!colin || (r + 2 >= H)) y2 = inf4();
        W4 o4 = pipe_step(s2, y2, colin && (r + 1 < H));

        if (wr) {
            float2 oa = __half22float2(o4.lo);
            float2 ob = __half22float2(o4.hi);
            if (z < NB) {   // o = cl_pred pixels; also dice terms (exact fp32)
                float4 tv = *(const float4*)(tb + off);
                float4 pv = *(const float4*)(pb + off);
                s0  += oa.x * tv.x + oa.y * tv.y + ob.x * tv.z + ob.y * tv.w;
                s1a += oa.x + oa.y + ob.x + ob.y;
                s2a += pv.x * tv.x + pv.y * tv.y + pv.z * tv.z + pv.w * tv.w;
                s3  += pv.x + pv.y + pv.z + pv.w;
                s4  += tv.x + tv.y + tv.z + tv.w;
            } else {        // o = target_skeleton pixels
                float4 pv = *(const float4*)(pb + off);
                s0  += oa.x * pv.x + oa.y * pv.y + ob.x * pv.z + ob.y * pv.w;
                s1a += oa.x + oa.y + ob.x + ob.y;
            }
        }
        off += W;
    }

    #pragma unroll
    for (int q = 16; q; q >>= 1) {
        s0  += __shfl_down_sync(0xffffffffu, s0, q);
        s1a += __shfl_down_sync(0xffffffffu, s1a, q);
        s2a += __shfl_down_sync(0xffffffffu, s2a, q);
        s3  += __shfl_down_sync(0xffffffffu, s3, q);
        s4  += __shfl_down_sync(0xffffffffu, s4, q);
    }
    __shared__ float sred[WPB][5];
    if (lane == 0) {
        sred[warp][0] = s0; sred[warp][1] = s1a; sred[warp][2] = s2a;
        sred[warp][3] = s3; sred[warp][4] = s4;
    }
    __syncthreads();
    if (threadIdx.x < 5) {
        float vv = 0;
        #pragma unroll
        for (int w = 0; w < WPB; w++) vv += sred[w][threadIdx.x];
        int q = threadIdx.x;
        if (z < NB) {
            int base = (q == 0) ? 0 : (q == 1) ? 64 : (q == 2) ? 256 : (q == 3) ? 320 : 384;
            atomicAdd(&g_acc[base + b], vv);
        } else if (q < 2) {
            atomicAdd(&g_acc[(q == 0 ? 128 : 192) + b], vv);
        }
    }
}

// ---------------------------------------------------------------------------
__global__ void zero_acc() {
    int i = threadIdx.x;
    if (i < 448) g_acc[i] = 0.0f;
}

__global__ void finalize_kernel(float* __restrict__ out) {
    int b = threadIdx.x;  // 64 threads
    float ifl = (g_acc[b] + 1.0f) / (g_acc[64 + b] + 1.0f);
    float tfl = (g_acc[128 + b] + 1.0f) / (g_acc[192 + b] + 1.0f);
    float it = ifl * tfl;
    float s  = ifl + tfl;
    float pt = g_acc[256 + b];
    float sp = g_acc[320 + b];
    float st = g_acc[384 + b];
    #pragma unroll
    for (int o = 16; o; o >>= 1) {
        it += __shfl_down_sync(0xffffffffu, it, o);
        s  += __shfl_down_sync(0xffffffffu, s,  o);
        pt += __shfl_down_sync(0xffffffffu, pt, o);
        sp += __shfl_down_sync(0xffffffffu, sp, o);
        st += __shfl_down_sync(0xffffffffu, st, o);
    }
    __shared__ float sh[5][2];
    if ((threadIdx.x & 31) == 0) {
        int w = threadIdx.x >> 5;
        sh[0][w] = it; sh[1][w] = s; sh[2][w] = pt; sh[3][w] = sp; sh[4][w] = st;
    }
    __syncthreads();
    if (threadIdx.x == 0) {
        float IT = sh[0][0] + sh[0][1];
        float S  = sh[1][0] + sh[1][1];
        float I  = sh[2][0] + sh[2][1];
        float Sp = sh[3][0] + sh[3][1];
        float St = sh[4][0] + sh[4][1];
        float dice   = 1.0f - (2.0f * I + 1e-6f) / (Sp + St + 1e-6f);
        float cldice = 1.0f - 2.0f * IT / S;
        out[0] = 0.8f * dice + 0.2f * cldice;
    }
}

// ---------------------------------------------------------------------------
extern "C" void kernel_launch(void* const* d_in, const int* in_sizes, int n_in,
                              void* d_out, int out_size) {
    const float* pred   = (const float*)d_in[0];
    const float* target = (const float*)d_in[1];
    float* out = (float*)d_out;

    zero_acc<<<1, 448>>>();

    dim3 blk(128);
    dim3 grd(NSTRIP, NZ, NRG);  // 5 x 128 x 4 = 2560 blocks (128 thr)

    skel2<<<grd, blk>>>(0, pred, target);   // iters 1-2: inputs -> A
    skel2<<<grd, blk>>>(1, pred, target);   // iters 3-4: A -> B
    skel2<<<grd, blk>>>(2, pred, target);   // iters 5-6: B -> A
    skel2<<<grd, blk>>>(1, pred, target);   // iters 7-8: A -> B
    skel2_last<<<grd, blk>>>(pred, target); // iters 9-10 + reductions (reads B)

    finalize_kernel<<<1, 64>>>(out);
}